// round 9
// baseline (speedup 1.0000x reference)
#include <cuda_runtime.h>
#include <cuda_bf16.h>
#include <math.h>

// Problem constants
#define EMBED 256
#define HID   1024
#define NEXP  4
#define WIN   16
#define BB    4
#define TT    4096
#define BT    (BB*TT)   // 16384

// ---------------- scratch (device globals; no runtime allocation) ------------
__device__ float g_h   [BT * EMBED];          // h (ln1 out), reused as h2
__device__ float g_qkv [BT * 3 * EMBED];      // qkv
__device__ float g_vpre[BT * EMBED];          // inclusive prefix sum of v over t
__device__ float g_csum[BB * 32 * EMBED];     // per-chunk totals for the scan
__device__ float g_aout[BT * EMBED];          // attention out * gate
__device__ float g_x1  [BT * EMBED];          // x + attn branch
__device__ float g_gate[BT * NEXP];           // gates
__device__ float g_hid [BT * HID];            // expert hidden

// ---------------- LayerNorm (one block per token, 256 threads) ---------------
__global__ void ln_kernel(const float* __restrict__ x,
                          const float* __restrict__ g,
                          const float* __restrict__ b,
                          float* __restrict__ out)
{
    int m = blockIdx.x;
    int c = threadIdx.x;
    float v = x[(size_t)m * EMBED + c];
    float s = v, sq = v * v;
    __shared__ float sbuf[16];
#pragma unroll
    for (int o = 16; o; o >>= 1) {
        s  += __shfl_xor_sync(0xffffffffu, s,  o);
        sq += __shfl_xor_sync(0xffffffffu, sq, o);
    }
    int w = c >> 5, lane = c & 31;
    if (lane == 0) { sbuf[w] = s; sbuf[8 + w] = sq; }
    __syncthreads();
    float mean = 0.f, m2 = 0.f;
#pragma unroll
    for (int i = 0; i < 8; ++i) { mean += sbuf[i]; m2 += sbuf[8 + i]; }
    mean *= (1.f / EMBED);
    m2 = m2 * (1.f / EMBED) - mean * mean;
    float inv = rsqrtf(m2 + 1e-5f);
    out[(size_t)m * EMBED + c] = (v - mean) * inv * g[c] + b[c];
}

// ---------------- LN2 + gating softmax (fused) --------------------------------
__global__ void ln2_gate_kernel(const float* __restrict__ x,
                                const float* __restrict__ g,
                                const float* __restrict__ b,
                                const float* __restrict__ gw,   // [EMBED, NEXP]
                                const float* __restrict__ gb,   // [NEXP]
                                float* __restrict__ hout,
                                float* __restrict__ gates)
{
    int m = blockIdx.x;
    int c = threadIdx.x;
    float v = x[(size_t)m * EMBED + c];
    float s = v, sq = v * v;
    __shared__ float sbuf[16];
    __shared__ float sh[EMBED];
    __shared__ float lg[NEXP];
#pragma unroll
    for (int o = 16; o; o >>= 1) {
        s  += __shfl_xor_sync(0xffffffffu, s,  o);
        sq += __shfl_xor_sync(0xffffffffu, sq, o);
    }
    int w = c >> 5, lane = c & 31;
    if (lane == 0) { sbuf[w] = s; sbuf[8 + w] = sq; }
    __syncthreads();
    float mean = 0.f, m2 = 0.f;
#pragma unroll
    for (int i = 0; i < 8; ++i) { mean += sbuf[i]; m2 += sbuf[8 + i]; }
    mean *= (1.f / EMBED);
    m2 = m2 * (1.f / EMBED) - mean * mean;
    float inv = rsqrtf(m2 + 1e-5f);
    float hv = (v - mean) * inv * g[c] + b[c];
    sh[c] = hv;
    hout[(size_t)m * EMBED + c] = hv;
    __syncthreads();
    if (w < NEXP) {
        float d = 0.f;
#pragma unroll
        for (int i = 0; i < 8; ++i) {
            int cc = lane + 32 * i;
            d += sh[cc] * gw[cc * NEXP + w];
        }
#pragma unroll
        for (int o = 16; o; o >>= 1) d += __shfl_xor_sync(0xffffffffu, d, o);
        if (lane == 0) lg[w] = d + gb[w];
    }
    __syncthreads();
    if (c == 0) {
        float mx = fmaxf(fmaxf(lg[0], lg[1]), fmaxf(lg[2], lg[3]));
        float e0 = expf(lg[0] - mx), e1 = expf(lg[1] - mx);
        float e2 = expf(lg[2] - mx), e3 = expf(lg[3] - mx);
        float Z = e0 + e1 + e2 + e3;
        float iZ = 1.f / Z;
        gates[(size_t)m * NEXP + 0] = e0 * iZ;
        gates[(size_t)m * NEXP + 1] = e1 * iZ;
        gates[(size_t)m * NEXP + 2] = e2 * iZ;
        gates[(size_t)m * NEXP + 3] = e3 * iZ;
    }
}

// ---------------- V prefix scan (2 phase) ------------------------------------
// phase 1: per-chunk (128 steps) inclusive scan + chunk totals
__global__ void prefix1(const float* __restrict__ qkv,
                        float* __restrict__ vpre,
                        float* __restrict__ csum)
{
    int b = blockIdx.y, chunk = blockIdx.x, c = threadIdx.x;
    float s = 0.f;
    int tbase = chunk * 128;
#pragma unroll 4
    for (int i = 0; i < 128; ++i) {
        int t = tbase + i;
        s += qkv[((size_t)(b * TT + t)) * (3 * EMBED) + 2 * EMBED + c];
        vpre[((size_t)(b * TT + t)) * EMBED + c] = s;
    }
    csum[(size_t)(b * 32 + chunk) * EMBED + c] = s;
}
// phase 2: add preceding chunk totals
__global__ void prefix2(const float* __restrict__ csum,
                        float* __restrict__ vpre)
{
    int b = blockIdx.y, chunk = blockIdx.x + 1, c = threadIdx.x;
    float off = 0.f;
    for (int k = 0; k < chunk; ++k)
        off += csum[(size_t)(b * 32 + k) * EMBED + c];
    int tbase = chunk * 128;
#pragma unroll 4
    for (int i = 0; i < 128; ++i)
        vpre[((size_t)(b * TT + tbase + i)) * EMBED + c] += off;
}

// ---------------- Windowed attention: one warp per query ---------------------
// softmax quirk: causal positions outside the window contribute exp(0) and
// weight * prefix-sum-of-v; in-window (17) positions use the real score.
__global__ void attn_kernel(const float* __restrict__ qkv,
                            const float* __restrict__ vpre,
                            const float* __restrict__ gate,
                            float* __restrict__ aout)
{
    int m = blockIdx.x * 8 + (threadIdx.x >> 5);
    int lane = threadIdx.x & 31;
    int b = m >> 12;         // /4096
    int t = m & 4095;

    const float* qrow = qkv + (size_t)m * (3 * EMBED);
    float q[8];
#pragma unroll
    for (int i = 0; i < 8; ++i) q[i] = qrow[lane + 32 * i];

    int nw = min(t + 1, WIN + 1);   // in-window count (<=17)
    float sc[WIN + 1];
    for (int j = 0; j < nw; ++j) {
        const float* krow = qkv + (size_t)(m - j) * (3 * EMBED) + EMBED;
        float d = 0.f;
#pragma unroll
        for (int i = 0; i < 8; ++i) d += q[i] * krow[lane + 32 * i];
#pragma unroll
        for (int o = 16; o; o >>= 1) d += __shfl_xor_sync(0xffffffffu, d, o);
        sc[j] = d * 0.0625f;   // 1/sqrt(256)
    }
    bool has_out = (t >= WIN + 1);
    float mx = has_out ? 0.f : -1e30f;
    for (int j = 0; j < nw; ++j) mx = fmaxf(mx, sc[j]);

    float Z = 0.f;
    float acc[8];
#pragma unroll
    for (int i = 0; i < 8; ++i) acc[i] = 0.f;
    for (int j = 0; j < nw; ++j) {
        float w = expf(sc[j] - mx);
        Z += w;
        const float* vrow = qkv + (size_t)(m - j) * (3 * EMBED) + 2 * EMBED;
#pragma unroll
        for (int i = 0; i < 8; ++i) acc[i] += w * vrow[lane + 32 * i];
    }
    if (has_out) {
        float w0 = expf(-mx);
        float cnt = (float)(t - WIN);           // number of out-of-window causal positions
        Z += cnt * w0;
        const float* p = vpre + (size_t)(b * TT + (t - WIN - 1)) * EMBED;
#pragma unroll
        for (int i = 0; i < 8; ++i) acc[i] += w0 * p[lane + 32 * i];
    }
    float iZ = 1.f / Z;
#pragma unroll
    for (int i = 0; i < 8; ++i) {
        int c = lane + 32 * i;
        aout[(size_t)m * EMBED + c] = acc[i] * iZ * gate[c];
    }
}

// ---------------- fp32 SGEMM 128x128x8, 8x8 per thread, epilogue modes -------
// MODE 0: C = A@B + bias
// MODE 1: C = res + A@B + bias
// MODE 2: C = gelu_exact(A@B + bias)
// MODE 3: C += gates[m,e] * (A@B + bias)
template <int MODE>
__global__ __launch_bounds__(256, 2)
void gemm_k(const float* __restrict__ A, const float* __restrict__ B,
            const float* __restrict__ bias, const float* __restrict__ res,
            const float* __restrict__ gates, int eidx,
            float* __restrict__ C, int M, int N, int K)
{
    __shared__ float As[8][128];
    __shared__ float Bs[8][128];
    int tid = threadIdx.x;
    int bm = blockIdx.y * 128;
    int bn = blockIdx.x * 128;
    int tx = tid & 15, ty = tid >> 4;

    float acc[8][8];
#pragma unroll
    for (int i = 0; i < 8; ++i)
#pragma unroll
        for (int j = 0; j < 8; ++j) acc[i][j] = 0.f;

    int arow = tid >> 1;
    int acol = (tid & 1) * 4;
    int brow = tid >> 5;
    int bcol = (tid & 31) * 4;
    const float* Aptr = A + (size_t)(bm + arow) * K + acol;
    const float* Bptr = B + (size_t)brow * N + bn + bcol;

    for (int k0 = 0; k0 < K; k0 += 8) {
        float4 av = *(const float4*)(Aptr + k0);
        float4 bv = *(const float4*)(Bptr + (size_t)k0 * N);
        __syncthreads();
        As[acol + 0][arow] = av.x;
        As[acol + 1][arow] = av.y;
        As[acol + 2][arow] = av.z;
        As[acol + 3][arow] = av.w;
        *(float4*)&Bs[brow][bcol] = bv;
        __syncthreads();
#pragma unroll
        for (int k = 0; k < 8; ++k) {
            float a[8], bvv[8];
            float4 a0 = *(const float4*)&As[k][ty * 8];
            float4 a1 = *(const float4*)&As[k][ty * 8 + 4];
            float4 b0 = *(const float4*)&Bs[k][tx * 8];
            float4 b1 = *(const float4*)&Bs[k][tx * 8 + 4];
            a[0]=a0.x; a[1]=a0.y; a[2]=a0.z; a[3]=a0.w;
            a[4]=a1.x; a[5]=a1.y; a[6]=a1.z; a[7]=a1.w;
            bvv[0]=b0.x; bvv[1]=b0.y; bvv[2]=b0.z; bvv[3]=b0.w;
            bvv[4]=b1.x; bvv[5]=b1.y; bvv[6]=b1.z; bvv[7]=b1.w;
#pragma unroll
            for (int i = 0; i < 8; ++i)
#pragma unroll
                for (int j = 0; j < 8; ++j)
                    acc[i][j] += a[i] * bvv[j];
        }
    }

#pragma unroll
    for (int i = 0; i < 8; ++i) {
        int r = bm + ty * 8 + i;
        float gv = 0.f;
        if (MODE == 3) gv = gates[(size_t)r * NEXP + eidx];
#pragma unroll
        for (int j = 0; j < 8; ++j) {
            int c = bn + tx * 8 + j;
            float v = acc[i][j] + bias[c];
            size_t o = (size_t)r * N + c;
            if (MODE == 0) {
                C[o] = v;
            } else if (MODE == 1) {
                C[o] = res[o] + v;
            } else if (MODE == 2) {
                C[o] = 0.5f * v * (1.f + erff(v * 0.70710678118654752f));
            } else {
                C[o] += gv * v;
            }
        }
    }
}

// ---------------- launch ------------------------------------------------------
extern "C" void kernel_launch(void* const* d_in, const int* in_sizes, int n_in,
                              void* d_out, int out_size)
{
    const float* x       = (const float*)d_in[0];
    const float* ln1_g   = (const float*)d_in[1];
    const float* ln1_b   = (const float*)d_in[2];
    const float* qkv_w   = (const float*)d_in[3];
    const float* qkv_b   = (const float*)d_in[4];
    const float* proj_w  = (const float*)d_in[5];
    const float* proj_b  = (const float*)d_in[6];
    const float* a_gate  = (const float*)d_in[7];
    const float* ln2_g   = (const float*)d_in[8];
    const float* ln2_b   = (const float*)d_in[9];
    const float* gat_w   = (const float*)d_in[10];
    const float* gat_b   = (const float*)d_in[11];
    const float* e_w1    = (const float*)d_in[12];
    const float* e_b1    = (const float*)d_in[13];
    const float* e_w2    = (const float*)d_in[14];
    const float* e_b2    = (const float*)d_in[15];
    float* out = (float*)d_out;

    float *h, *qkv, *vpre, *csum, *aout, *x1, *gates, *hid;
    cudaGetSymbolAddress((void**)&h,    g_h);
    cudaGetSymbolAddress((void**)&qkv,  g_qkv);
    cudaGetSymbolAddress((void**)&vpre, g_vpre);
    cudaGetSymbolAddress((void**)&csum, g_csum);
    cudaGetSymbolAddress((void**)&aout, g_aout);
    cudaGetSymbolAddress((void**)&x1,   g_x1);
    cudaGetSymbolAddress((void**)&gates, g_gate);
    cudaGetSymbolAddress((void**)&hid,  g_hid);

    // 1) h = LN1(x)
    ln_kernel<<<BT, 256>>>(x, ln1_g, ln1_b, h);

    // 2) qkv = h @ qkv_w + qkv_b   [BT, 768]
    gemm_k<0><<<dim3(768 / 128, BT / 128), 256>>>(
        h, qkv_w, qkv_b, nullptr, nullptr, 0, qkv, BT, 3 * EMBED, EMBED);

    // 3) prefix sums of v over t
    prefix1<<<dim3(32, BB), 256>>>(qkv, vpre, csum);
    prefix2<<<dim3(31, BB), 256>>>(csum, vpre);

    // 4) attention (one warp per query)
    attn_kernel<<<BT / 8, 256>>>(qkv, vpre, a_gate, aout);

    // 5) x1 = x + aout @ proj_w + proj_b
    gemm_k<1><<<dim3(EMBED / 128, BT / 128), 256>>>(
        aout, proj_w, proj_b, x, nullptr, 0, x1, BT, EMBED, EMBED);

    // 6) h2 = LN2(x1), gates = softmax(h2 @ gating_w + gating_b)
    ln2_gate_kernel<<<BT, 256>>>(x1, ln2_g, ln2_b, gat_w, gat_b, h, gates);

    // 7) out starts at x1
    cudaMemcpyAsync(out, x1, (size_t)BT * EMBED * sizeof(float),
                    cudaMemcpyDeviceToDevice);

    // 8) dense MoE: out += gates[:,e] * (gelu(h2@w1_e + b1_e) @ w2_e + b2_e)
    for (int e = 0; e < NEXP; ++e) {
        gemm_k<2><<<dim3(HID / 128, BT / 128), 256>>>(
            h, e_w1 + (size_t)e * EMBED * HID, e_b1 + (size_t)e * HID,
            nullptr, nullptr, 0, hid, BT, HID, EMBED);
        gemm_k<3><<<dim3(EMBED / 128, BT / 128), 256>>>(
            hid, e_w2 + (size_t)e * HID * EMBED, e_b2 + (size_t)e * EMBED,
            nullptr, gates, e, out, BT, EMBED, HID);
    }
}

// round 10
// speedup vs baseline: 1.0008x; 1.0008x over previous
#include <cuda_runtime.h>
#include <cuda_bf16.h>
#include <math.h>

// Problem constants
#define EMBED 256
#define HID   1024
#define NEXP  4
#define WIN   16
#define BB    4
#define TT    4096
#define BT    (BB*TT)   // 16384

// ---------------- scratch (device globals; no runtime allocation) ------------
__device__ float g_h   [BT * EMBED];          // h (ln1 out), reused as h2
__device__ float g_qkv [BT * 3 * EMBED];      // qkv
__device__ float g_vpre[BT * EMBED];          // inclusive prefix sum of v over t
__device__ float g_csum[BB * 32 * EMBED];     // per-chunk totals for the scan
__device__ float g_aout[BT * EMBED];          // attention out * gate
__device__ float g_x1  [BT * EMBED];          // x + attn branch
__device__ float g_gate[BT * NEXP];           // gates
__device__ float g_hid [BT * HID];            // expert hidden

// ---------------- LayerNorm (one block per token, 256 threads) ---------------
__global__ void ln_kernel(const float* __restrict__ x,
                          const float* __restrict__ g,
                          const float* __restrict__ b,
                          float* __restrict__ out)
{
    int m = blockIdx.x;
    int c = threadIdx.x;
    float v = x[(size_t)m * EMBED + c];
    float s = v, sq = v * v;
    __shared__ float sbuf[16];
#pragma unroll
    for (int o = 16; o; o >>= 1) {
        s  += __shfl_xor_sync(0xffffffffu, s,  o);
        sq += __shfl_xor_sync(0xffffffffu, sq, o);
    }
    int w = c >> 5, lane = c & 31;
    if (lane == 0) { sbuf[w] = s; sbuf[8 + w] = sq; }
    __syncthreads();
    float mean = 0.f, m2 = 0.f;
#pragma unroll
    for (int i = 0; i < 8; ++i) { mean += sbuf[i]; m2 += sbuf[8 + i]; }
    mean *= (1.f / EMBED);
    m2 = m2 * (1.f / EMBED) - mean * mean;
    float inv = rsqrtf(m2 + 1e-5f);
    out[(size_t)m * EMBED + c] = (v - mean) * inv * g[c] + b[c];
}

// ---------------- LN2 + gating softmax (fused) --------------------------------
__global__ void ln2_gate_kernel(const float* __restrict__ x,
                                const float* __restrict__ g,
                                const float* __restrict__ b,
                                const float* __restrict__ gw,   // [EMBED, NEXP]
                                const float* __restrict__ gb,   // [NEXP]
                                float* __restrict__ hout,
                                float* __restrict__ gates)
{
    int m = blockIdx.x;
    int c = threadIdx.x;
    float v = x[(size_t)m * EMBED + c];
    float s = v, sq = v * v;
    __shared__ float sbuf[16];
    __shared__ float sh[EMBED];
    __shared__ float lg[NEXP];
#pragma unroll
    for (int o = 16; o; o >>= 1) {
        s  += __shfl_xor_sync(0xffffffffu, s,  o);
        sq += __shfl_xor_sync(0xffffffffu, sq, o);
    }
    int w = c >> 5, lane = c & 31;
    if (lane == 0) { sbuf[w] = s; sbuf[8 + w] = sq; }
    __syncthreads();
    float mean = 0.f, m2 = 0.f;
#pragma unroll
    for (int i = 0; i < 8; ++i) { mean += sbuf[i]; m2 += sbuf[8 + i]; }
    mean *= (1.f / EMBED);
    m2 = m2 * (1.f / EMBED) - mean * mean;
    float inv = rsqrtf(m2 + 1e-5f);
    float hv = (v - mean) * inv * g[c] + b[c];
    sh[c] = hv;
    hout[(size_t)m * EMBED + c] = hv;
    __syncthreads();
    if (w < NEXP) {
        float d = 0.f;
#pragma unroll
        for (int i = 0; i < 8; ++i) {
            int cc = lane + 32 * i;
            d += sh[cc] * gw[cc * NEXP + w];
        }
#pragma unroll
        for (int o = 16; o; o >>= 1) d += __shfl_xor_sync(0xffffffffu, d, o);
        if (lane == 0) lg[w] = d + gb[w];
    }
    __syncthreads();
    if (c == 0) {
        float mx = fmaxf(fmaxf(lg[0], lg[1]), fmaxf(lg[2], lg[3]));
        float e0 = expf(lg[0] - mx), e1 = expf(lg[1] - mx);
        float e2 = expf(lg[2] - mx), e3 = expf(lg[3] - mx);
        float Z = e0 + e1 + e2 + e3;
        float iZ = 1.f / Z;
        gates[(size_t)m * NEXP + 0] = e0 * iZ;
        gates[(size_t)m * NEXP + 1] = e1 * iZ;
        gates[(size_t)m * NEXP + 2] = e2 * iZ;
        gates[(size_t)m * NEXP + 3] = e3 * iZ;
    }
}

// ---------------- V prefix scan (2 phase) ------------------------------------
// phase 1: per-chunk (128 steps) inclusive scan + chunk totals
__global__ void prefix1(const float* __restrict__ qkv,
                        float* __restrict__ vpre,
                        float* __restrict__ csum)
{
    int b = blockIdx.y, chunk = blockIdx.x, c = threadIdx.x;
    float s = 0.f;
    int tbase = chunk * 128;
#pragma unroll 4
    for (int i = 0; i < 128; ++i) {
        int t = tbase + i;
        s += qkv[((size_t)(b * TT + t)) * (3 * EMBED) + 2 * EMBED + c];
        vpre[((size_t)(b * TT + t)) * EMBED + c] = s;
    }
    csum[(size_t)(b * 32 + chunk) * EMBED + c] = s;
}
// phase 2: add preceding chunk totals
__global__ void prefix2(const float* __restrict__ csum,
                        float* __restrict__ vpre)
{
    int b = blockIdx.y, chunk = blockIdx.x + 1, c = threadIdx.x;
    float off = 0.f;
    for (int k = 0; k < chunk; ++k)
        off += csum[(size_t)(b * 32 + k) * EMBED + c];
    int tbase = chunk * 128;
#pragma unroll 4
    for (int i = 0; i < 128; ++i)
        vpre[((size_t)(b * TT + tbase + i)) * EMBED + c] += off;
}

// ---------------- Windowed attention: one warp per query ---------------------
// softmax quirk: causal positions outside the window contribute exp(0) and
// weight * prefix-sum-of-v; in-window (17) positions use the real score.
__global__ void attn_kernel(const float* __restrict__ qkv,
                            const float* __restrict__ vpre,
                            const float* __restrict__ gate,
                            float* __restrict__ aout)
{
    int m = blockIdx.x * 8 + (threadIdx.x >> 5);
    int lane = threadIdx.x & 31;
    int b = m >> 12;         // /4096
    int t = m & 4095;

    const float* qrow = qkv + (size_t)m * (3 * EMBED);
    float q[8];
#pragma unroll
    for (int i = 0; i < 8; ++i) q[i] = qrow[lane + 32 * i];

    int nw = min(t + 1, WIN + 1);   // in-window count (<=17)
    float sc[WIN + 1];
    for (int j = 0; j < nw; ++j) {
        const float* krow = qkv + (size_t)(m - j) * (3 * EMBED) + EMBED;
        float d = 0.f;
#pragma unroll
        for (int i = 0; i < 8; ++i) d += q[i] * krow[lane + 32 * i];
#pragma unroll
        for (int o = 16; o; o >>= 1) d += __shfl_xor_sync(0xffffffffu, d, o);
        sc[j] = d * 0.0625f;   // 1/sqrt(256)
    }
    bool has_out = (t >= WIN + 1);
    float mx = has_out ? 0.f : -1e30f;
    for (int j = 0; j < nw; ++j) mx = fmaxf(mx, sc[j]);

    float Z = 0.f;
    float acc[8];
#pragma unroll
    for (int i = 0; i < 8; ++i) acc[i] = 0.f;
    for (int j = 0; j < nw; ++j) {
        float w = expf(sc[j] - mx);
        Z += w;
        const float* vrow = qkv + (size_t)(m - j) * (3 * EMBED) + 2 * EMBED;
#pragma unroll
        for (int i = 0; i < 8; ++i) acc[i] += w * vrow[lane + 32 * i];
    }
    if (has_out) {
        float w0 = expf(-mx);
        float cnt = (float)(t - WIN);           // number of out-of-window causal positions
        Z += cnt * w0;
        const float* p = vpre + (size_t)(b * TT + (t - WIN - 1)) * EMBED;
#pragma unroll
        for (int i = 0; i < 8; ++i) acc[i] += w0 * p[lane + 32 * i];
    }
    float iZ = 1.f / Z;
#pragma unroll
    for (int i = 0; i < 8; ++i) {
        int c = lane + 32 * i;
        aout[(size_t)m * EMBED + c] = acc[i] * iZ * gate[c];
    }
}

// ---------------- fp32 SGEMM 128x128x8, 8x8 per thread, epilogue modes -------
// MODE 0: C = A@B + bias
// MODE 1: C = res + A@B + bias
// MODE 2: C = gelu_exact(A@B + bias)
// MODE 3: C += gates[m,e] * (A@B + bias)
template <int MODE>
__global__ __launch_bounds__(256, 2)
void gemm_k(const float* __restrict__ A, const float* __restrict__ B,
            const float* __restrict__ bias, const float* __restrict__ res,
            const float* __restrict__ gates, int eidx,
            float* __restrict__ C, int M, int N, int K)
{
    __shared__ float As[8][128];
    __shared__ float Bs[8][128];
    int tid = threadIdx.x;
    int bm = blockIdx.y * 128;
    int bn = blockIdx.x * 128;
    int tx = tid & 15, ty = tid >> 4;

    float acc[8][8];
#pragma unroll
    for (int i = 0; i < 8; ++i)
#pragma unroll
        for (int j = 0; j < 8; ++j) acc[i][j] = 0.f;

    int arow = tid >> 1;
    int acol = (tid & 1) * 4;
    int brow = tid >> 5;
    int bcol = (tid & 31) * 4;
    const float* Aptr = A + (size_t)(bm + arow) * K + acol;
    const float* Bptr = B + (size_t)brow * N + bn + bcol;

    for (int k0 = 0; k0 < K; k0 += 8) {
        float4 av = *(const float4*)(Aptr + k0);
        float4 bv = *(const float4*)(Bptr + (size_t)k0 * N);
        __syncthreads();
        As[acol + 0][arow] = av.x;
        As[acol + 1][arow] = av.y;
        As[acol + 2][arow] = av.z;
        As[acol + 3][arow] = av.w;
        *(float4*)&Bs[brow][bcol] = bv;
        __syncthreads();
#pragma unroll
        for (int k = 0; k < 8; ++k) {
            float a[8], bvv[8];
            float4 a0 = *(const float4*)&As[k][ty * 8];
            float4 a1 = *(const float4*)&As[k][ty * 8 + 4];
            float4 b0 = *(const float4*)&Bs[k][tx * 8];
            float4 b1 = *(const float4*)&Bs[k][tx * 8 + 4];
            a[0]=a0.x; a[1]=a0.y; a[2]=a0.z; a[3]=a0.w;
            a[4]=a1.x; a[5]=a1.y; a[6]=a1.z; a[7]=a1.w;
            bvv[0]=b0.x; bvv[1]=b0.y; bvv[2]=b0.z; bvv[3]=b0.w;
            bvv[4]=b1.x; bvv[5]=b1.y; bvv[6]=b1.z; bvv[7]=b1.w;
#pragma unroll
            for (int i = 0; i < 8; ++i)
#pragma unroll
                for (int j = 0; j < 8; ++j)
                    acc[i][j] += a[i] * bvv[j];
        }
    }

#pragma unroll
    for (int i = 0; i < 8; ++i) {
        int r = bm + ty * 8 + i;
        float gv = 0.f;
        if (MODE == 3) gv = gates[(size_t)r * NEXP + eidx];
#pragma unroll
        for (int j = 0; j < 8; ++j) {
            int c = bn + tx * 8 + j;
            float v = acc[i][j] + bias[c];
            size_t o = (size_t)r * N + c;
            if (MODE == 0) {
                C[o] = v;
            } else if (MODE == 1) {
                C[o] = res[o] + v;
            } else if (MODE == 2) {
                C[o] = 0.5f * v * (1.f + erff(v * 0.70710678118654752f));
            } else {
                C[o] += gv * v;
            }
        }
    }
}

// ---------------- launch ------------------------------------------------------
extern "C" void kernel_launch(void* const* d_in, const int* in_sizes, int n_in,
                              void* d_out, int out_size)
{
    const float* x       = (const float*)d_in[0];
    const float* ln1_g   = (const float*)d_in[1];
    const float* ln1_b   = (const float*)d_in[2];
    const float* qkv_w   = (const float*)d_in[3];
    const float* qkv_b   = (const float*)d_in[4];
    const float* proj_w  = (const float*)d_in[5];
    const float* proj_b  = (const float*)d_in[6];
    const float* a_gate  = (const float*)d_in[7];
    const float* ln2_g   = (const float*)d_in[8];
    const float* ln2_b   = (const float*)d_in[9];
    const float* gat_w   = (const float*)d_in[10];
    const float* gat_b   = (const float*)d_in[11];
    const float* e_w1    = (const float*)d_in[12];
    const float* e_b1    = (const float*)d_in[13];
    const float* e_w2    = (const float*)d_in[14];
    const float* e_b2    = (const float*)d_in[15];
    float* out = (float*)d_out;

    float *h, *qkv, *vpre, *csum, *aout, *x1, *gates, *hid;
    cudaGetSymbolAddress((void**)&h,    g_h);
    cudaGetSymbolAddress((void**)&qkv,  g_qkv);
    cudaGetSymbolAddress((void**)&vpre, g_vpre);
    cudaGetSymbolAddress((void**)&csum, g_csum);
    cudaGetSymbolAddress((void**)&aout, g_aout);
    cudaGetSymbolAddress((void**)&x1,   g_x1);
    cudaGetSymbolAddress((void**)&gates, g_gate);
    cudaGetSymbolAddress((void**)&hid,  g_hid);

    // 1) h = LN1(x)
    ln_kernel<<<BT, 256>>>(x, ln1_g, ln1_b, h);

    // 2) qkv = h @ qkv_w + qkv_b   [BT, 768]
    gemm_k<0><<<dim3(768 / 128, BT / 128), 256>>>(
        h, qkv_w, qkv_b, nullptr, nullptr, 0, qkv, BT, 3 * EMBED, EMBED);

    // 3) prefix sums of v over t
    prefix1<<<dim3(32, BB), 256>>>(qkv, vpre, csum);
    prefix2<<<dim3(31, BB), 256>>>(csum, vpre);

    // 4) attention (one warp per query)
    attn_kernel<<<BT / 8, 256>>>(qkv, vpre, a_gate, aout);

    // 5) x1 = x + aout @ proj_w + proj_b
    gemm_k<1><<<dim3(EMBED / 128, BT / 128), 256>>>(
        aout, proj_w, proj_b, x, nullptr, 0, x1, BT, EMBED, EMBED);

    // 6) h2 = LN2(x1), gates = softmax(h2 @ gating_w + gating_b)
    ln2_gate_kernel<<<BT, 256>>>(x1, ln2_g, ln2_b, gat_w, gat_b, h, gates);

    // 7) out starts at x1
    cudaMemcpyAsync(out, x1, (size_t)BT * EMBED * sizeof(float),
                    cudaMemcpyDeviceToDevice);

    // 8) dense MoE: out += gates[:,e] * (gelu(h2@w1_e + b1_e) @ w2_e + b2_e)
    for (int e = 0; e < NEXP; ++e) {
        gemm_k<2><<<dim3(HID / 128, BT / 128), 256>>>(
            h, e_w1 + (size_t)e * EMBED * HID, e_b1 + (size_t)e * HID,
            nullptr, nullptr, 0, hid, BT, HID, EMBED);
        gemm_k<3><<<dim3(EMBED / 128, BT / 128), 256>>>(
            hid, e_w2 + (size_t)e * HID * EMBED, e_b2 + (size_t)e * EMBED,
            nullptr, gates, e, out, BT, EMBED, HID);
    }
}